// round 10
// baseline (speedup 1.0000x reference)
#include <cuda_runtime.h>
#include <math.h>
#include <string.h>
#include <stdint.h>

// Problem constants
#define NN   1024
#define MUL  128
#define CH   128
#define RBq  20
#define RAq  19
#define DX   9     // (L1+1)^2 = (L2+1)^2
#define DZ   25    // (LZ+1)^2
#define MAXG 480

#define SCALE_IN  0.08838834764831845f   // 1/sqrt(128)
#define SCALE_OUT 0.08838834764831845f   // 1/sqrt(128)

// Sparse Gaunt table, passed by value as kernel parameter (constant memory).
struct GTab {
    int   start[DZ + 1];
    int   idx[MAXG];       // (d1 << 8) | d2
    float coef[MAXG];
};

// Intermediates
__device__ float g_xt [NN * DX * MUL];   // x transposed [n][d][m]
__device__ float g_yt [NN * DX * MUL];   // y transposed [n][d][m]
__device__ float g_xct[NN * DX * CH];    // [n][d][c]
__device__ float g_yct[NN * DX * CH];
__device__ float g_zt [NN * DZ * CH];    // [n][d][c]

// ---------------------------------------------------------------------------
// cp.async helpers
// ---------------------------------------------------------------------------
__device__ __forceinline__ void cp_async16(uint32_t dst, const void* src) {
    asm volatile("cp.async.cg.shared.global [%0], [%1], 16;\n" :: "r"(dst), "l"(src));
}
__device__ __forceinline__ void cp_commit() {
    asm volatile("cp.async.commit_group;\n" ::: "memory");
}
template<int N> __device__ __forceinline__ void cp_wait() {
    asm volatile("cp.async.wait_group %0;\n" :: "n"(N) : "memory");
}

// ---------------------------------------------------------------------------
// Host: build the Gaunt table (double precision, exact quadrature as ref)
// ---------------------------------------------------------------------------
static double assoc_legendre_h(int l, int m, double x) {
    double pmm = 1.0;
    if (m > 0) {
        double df = 1.0;
        for (int i = 1; i < 2 * m; i += 2) df *= (double)i;
        pmm = ((m & 1) ? -1.0 : 1.0) * df * pow(1.0 - x * x, 0.5 * m);
    }
    if (l == m) return pmm;
    double pmmp1 = x * (2 * m + 1) * pmm;
    if (l == m + 1) return pmmp1;
    double p = pmmp1;
    for (int ll = m + 2; ll <= l; ++ll) {
        p = ((2 * ll - 1) * x * pmmp1 - (ll + m - 1) * pmm) / (ll - m);
        pmm = pmmp1; pmmp1 = p;
    }
    return pmmp1;
}

static void build_gtab(GTab* gt) {
    double ct[RBq], qw[RBq];
    const int n = RBq;
    for (int i = 0; i < n; ++i) {
        double z = cos(M_PI * (i + 0.75) / (n + 0.5));
        double pp = 1.0;
        for (int it = 0; it < 100; ++it) {
            double p1 = 1.0, p2 = 0.0;
            for (int j = 1; j <= n; ++j) {
                double p3 = p2; p2 = p1;
                p1 = ((2.0 * j - 1.0) * z * p2 - (j - 1.0) * p3) / (double)j;
            }
            pp = n * (z * p1 - p2) / (z * z - 1.0);
            double dz = p1 / pp;
            z -= dz;
            if (fabs(dz) < 1e-15) break;
        }
        ct[i] = z;
        qw[i] = 2.0 / ((1.0 - z * z) * pp * pp);
    }

    static double Y[DZ][RBq][RAq];
    for (int l = 0; l <= 4; ++l) {
        for (int m = -l; m <= l; ++m) {
            int am = m < 0 ? -m : m;
            double f1 = 1.0, f2 = 1.0;
            for (int i = 2; i <= l - am; ++i) f1 *= (double)i;
            for (int i = 2; i <= l + am; ++i) f2 *= (double)i;
            double nlm = sqrt((2.0 * l + 1.0) / (4.0 * M_PI) * f1 / f2);
            for (int b = 0; b < RBq; ++b) {
                double P = assoc_legendre_h(l, am, ct[b]);
                for (int a = 0; a < RAq; ++a) {
                    double alpha = 2.0 * M_PI * (double)a / (double)RAq;
                    double ang;
                    if (m == 0)      ang = 1.0;
                    else if (m > 0)  ang = sqrt(2.0) * cos(m * alpha);
                    else             ang = sqrt(2.0) * sin(am * alpha);
                    Y[l * l + l + m][b][a] = nlm * P * ang;
                }
            }
        }
    }

    int cnt = 0;
    for (int d = 0; d < DZ; ++d) {
        gt->start[d] = cnt;
        for (int d1 = 0; d1 < DX; ++d1) {
            for (int d2 = 0; d2 < DX; ++d2) {
                double s = 0.0;
                for (int b = 0; b < RBq; ++b) {
                    double rs = 0.0;
                    for (int a = 0; a < RAq; ++a)
                        rs += Y[d][b][a] * Y[d1][b][a] * Y[d2][b][a];
                    s += rs * qw[b];
                }
                s *= 2.0 * M_PI / (double)RAq;
                if (fabs(s) > 1e-8 && cnt < MAXG) {
                    gt->idx[cnt]  = (d1 << 8) | d2;
                    gt->coef[cnt] = (float)s;
                    ++cnt;
                }
            }
        }
    }
    gt->start[DZ] = cnt;
    for (int k = cnt; k < MAXG; ++k) { gt->idx[k] = 0; gt->coef[k] = 0.0f; }
}

// ---------------------------------------------------------------------------
// Kernel 0: transpose x,y [n][m][9] -> [n][9][m]. 4 nodes/CTA, 256 threads.
// ---------------------------------------------------------------------------
__global__ void __launch_bounds__(256) k_tr(
    const float* __restrict__ x, const float* __restrict__ y)
{
    __shared__ float sm[4 * MUL * DX];   // 18432 B
    const int tid = threadIdx.x;
    const int n0  = blockIdx.x * 4;
    const int NB  = 4 * MUL * DX;        // 4608

    for (int pass = 0; pass < 2; ++pass) {
        const float* src = pass ? y    : x;
        float*       dst = pass ? g_yt : g_xt;

        __syncthreads();
        for (int i = tid; i < NB; i += 256)
            sm[i] = src[(size_t)n0 * (MUL * DX) + i];
        __syncthreads();
        for (int o = tid; o < NB; o += 256) {
            int j = o / (DX * MUL);
            int r = o - j * (DX * MUL);
            int d = r >> 7;              // r / 128
            int m = r & 127;
            dst[(size_t)n0 * (DX * MUL) + o] = sm[j * (MUL * DX) + m * DX + d];
        }
    }
}

// ---------------------------------------------------------------------------
// Shared GEMM machinery: CTA = 64 rows x 128 cols, K=128 in 4 chunks of 32,
// cp.async double-buffered, 256 threads, 4x8 micro-tile.
// ---------------------------------------------------------------------------
#define KC  32
#define PAK 36    // A row pitch (32 + 4): conflict-free, float4-aligned

// issue one stage of cp.async loads (A: 64 rows x KC, B: KC x 128)
__device__ __forceinline__ void gemm_load_stage(
    uint32_t As_u, uint32_t Bs_u, int buf,
    const float* Ab, int ldA, const float* Bb, int ko,
    int ar, int as, int bk, int be4)
{
    cp_async16(As_u + (((buf * 64 + ar)      * PAK + as * 4) << 2),
               Ab + (size_t)ar * ldA + ko + as * 4);
    cp_async16(As_u + (((buf * 64 + ar + 32) * PAK + as * 4) << 2),
               Ab + (size_t)(ar + 32) * ldA + ko + as * 4);
    #pragma unroll
    for (int s = 0; s < 4; ++s)
        cp_async16(Bs_u + (((buf * KC + bk + s * 8) * 128 + be4 * 4) << 2),
                   Bb + (size_t)(ko + bk + s * 8) * CH + be4 * 4);
    cp_commit();
}

__device__ __forceinline__ void gemm_compute_stage(
    const float* __restrict__ A, const float* __restrict__ B,
    int tm, int te, float acc[4][8])
{
    const float* a0p = A + (tm * 4 + 0) * PAK;
    const float* a1p = A + (tm * 4 + 1) * PAK;
    const float* a2p = A + (tm * 4 + 2) * PAK;
    const float* a3p = A + (tm * 4 + 3) * PAK;
    #pragma unroll 8
    for (int kk = 0; kk < KC; ++kk) {
        float a0 = a0p[kk];
        float a1 = a1p[kk];
        float a2 = a2p[kk];
        float a3 = a3p[kk];
        float4 b0 = *(const float4*)(B + kk * 128 + te * 4);
        float4 b1 = *(const float4*)(B + kk * 128 + 64 + te * 4);
        float bv[8] = {b0.x, b0.y, b0.z, b0.w, b1.x, b1.y, b1.z, b1.w};
        #pragma unroll
        for (int j = 0; j < 8; ++j) {
            acc[0][j] = fmaf(a0, bv[j], acc[0][j]);
            acc[1][j] = fmaf(a1, bv[j], acc[1][j]);
            acc[2][j] = fmaf(a2, bv[j], acc[2][j]);
            acc[3][j] = fmaf(a3, bv[j], acc[3][j]);
        }
    }
}

// full mainloop filling acc[4][8]
__device__ __forceinline__ void gemm_mainloop(
    const float* Ab, int ldA, const float* Bb,
    float* As, float* Bs, int tid, float acc[4][8])
{
    const int ar  = tid >> 3;
    const int as  = tid & 7;
    const int be4 = tid & 31;
    const int bk  = tid >> 5;
    const int tm  = tid >> 4;
    const int te  = tid & 15;

    uint32_t As_u = (uint32_t)__cvta_generic_to_shared(As);
    uint32_t Bs_u = (uint32_t)__cvta_generic_to_shared(Bs);

    #pragma unroll
    for (int i = 0; i < 4; ++i)
        #pragma unroll
        for (int j = 0; j < 8; ++j) acc[i][j] = 0.0f;

    gemm_load_stage(As_u, Bs_u, 0, Ab, ldA, Bb, 0,      ar, as, bk, be4);
    gemm_load_stage(As_u, Bs_u, 1, Ab, ldA, Bb, KC,     ar, as, bk, be4);

    // kb = 0
    cp_wait<1>(); __syncthreads();
    gemm_compute_stage(As, Bs, tm, te, acc);
    __syncthreads();
    gemm_load_stage(As_u, Bs_u, 0, Ab, ldA, Bb, 2 * KC, ar, as, bk, be4);

    // kb = 1
    cp_wait<1>(); __syncthreads();
    gemm_compute_stage(As + 64 * PAK, Bs + KC * 128, tm, te, acc);
    __syncthreads();
    gemm_load_stage(As_u, Bs_u, 1, Ab, ldA, Bb, 3 * KC, ar, as, bk, be4);

    // kb = 2
    cp_wait<1>(); __syncthreads();
    gemm_compute_stage(As, Bs, tm, te, acc);

    // kb = 3
    cp_wait<0>(); __syncthreads();
    gemm_compute_stage(As + 64 * PAK, Bs + KC * 128, tm, te, acc);
}

// ---------------------------------------------------------------------------
// Kernel 1: linear_in as d-batched SGEMM (cp.async pipeline).
// grid (16, 18): b = blockIdx.y -> (tensor, d).
// ---------------------------------------------------------------------------
__global__ void __launch_bounds__(256, 3) k_lin_gemm(
    const float* __restrict__ wx, const float* __restrict__ wy)
{
    extern __shared__ float sm[];
    float* As = sm;                    // [2][64][PAK]
    float* Bs = sm + 2 * 64 * PAK;     // [2][KC][128]

    const int b    = blockIdx.y;
    const int is_y = (b >= DX);
    const int d    = is_y ? (b - DX) : b;
    const int l    = (d >= 4) ? 2 : (d >= 1) ? 1 : 0;
    const int n0   = blockIdx.x * 64;
    const int tid  = threadIdx.x;

    const float* Ab = (is_y ? g_yt : g_xt) + (size_t)n0 * (DX * MUL) + (size_t)d * MUL;
    const float* Bb = (is_y ? wy : wx) + (size_t)l * (MUL * CH);
    float*       Cb = (is_y ? g_yct : g_xct) + (size_t)n0 * (DX * CH) + (size_t)d * CH;

    float acc[4][8];
    gemm_mainloop(Ab, DX * MUL, Bb, As, Bs, tid, acc);

    const int tm = tid >> 4;
    const int te = tid & 15;
    #pragma unroll
    for (int i = 0; i < 4; ++i) {
        float* cp = Cb + (size_t)(tm * 4 + i) * (DX * CH);
        float4 v0 = make_float4(acc[i][0] * SCALE_IN, acc[i][1] * SCALE_IN,
                                acc[i][2] * SCALE_IN, acc[i][3] * SCALE_IN);
        float4 v1 = make_float4(acc[i][4] * SCALE_IN, acc[i][5] * SCALE_IN,
                                acc[i][6] * SCALE_IN, acc[i][7] * SCALE_IN);
        *(float4*)(cp + te * 4)      = v0;
        *(float4*)(cp + 64 + te * 4) = v1;
    }
}

// ---------------------------------------------------------------------------
// Kernel 2: sparse Gaunt contraction. 2 nodes/CTA, 128 threads.
// ---------------------------------------------------------------------------
__global__ void __launch_bounds__(128) k_gaunt(GTab gt)
{
    __shared__ float xcs[2 * DX * CH];
    __shared__ float ycs[2 * DX * CH];

    const int t  = threadIdx.x;
    const int n0 = blockIdx.x * 2;

    for (int i = t; i < 2 * DX * CH; i += 128) {
        xcs[i] = g_xct[(size_t)n0 * DX * CH + i];
        ycs[i] = g_yct[(size_t)n0 * DX * CH + i];
    }
    __syncthreads();

    const float* x0 = xcs + t;
    const float* x1 = xcs + DX * CH + t;
    const float* y0 = ycs + t;
    const float* y1 = ycs + DX * CH + t;
    float* o0 = g_zt + (size_t)n0 * DZ * CH + t;
    float* o1 = o0 + DZ * CH;

    for (int d = 0; d < DZ; ++d) {
        float z0 = 0.0f, z1 = 0.0f;
        const int e0 = gt.start[d], e1 = gt.start[d + 1];
        for (int k = e0; k < e1; ++k) {
            const int   id = gt.idx[k];
            const float cf = gt.coef[k];
            const int a1 = (id >> 8) * CH;
            const int a2 = (id & 255) * CH;
            z0 = fmaf(cf, x0[a1] * y0[a2], z0);
            z1 = fmaf(cf, x1[a1] * y1[a2], z1);
        }
        o0[d * CH] = z0 * SCALE_OUT;
        o1[d * CH] = z1 * SCALE_OUT;
    }
}

// ---------------------------------------------------------------------------
// Kernel 3: linear_out as d-batched SGEMM (cp.async pipeline).
// ---------------------------------------------------------------------------
__global__ void __launch_bounds__(256, 3) k_out(
    const float* __restrict__ wz, float* __restrict__ out)
{
    extern __shared__ float sm[];
    float* As = sm;                    // [2][64][PAK]
    float* Bs = sm + 2 * 64 * PAK;     // [2][KC][128]

    const int d   = blockIdx.y;
    const int l   = (d >= 16) ? 4 : (d >= 9) ? 3 : (d >= 4) ? 2 : (d >= 1) ? 1 : 0;
    const int n0  = blockIdx.x * 64;
    const int tid = threadIdx.x;

    const float* Ab = g_zt + (size_t)n0 * (DZ * CH) + (size_t)d * CH;
    const float* Bb = wz + (size_t)l * (CH * CH);

    float acc[4][8];
    gemm_mainloop(Ab, DZ * CH, Bb, As, Bs, tid, acc);

    const int tm = tid >> 4;
    const int te = tid & 15;
    // store: out[n][e][d]
    #pragma unroll
    for (int i = 0; i < 4; ++i) {
        const int n = n0 + tm * 4 + i;
        float* op = out + (size_t)n * (CH * DZ) + d;
        #pragma unroll
        for (int j = 0; j < 8; ++j) {
            const int e = (j < 4) ? (te * 4 + j) : (64 + te * 4 + (j - 4));
            op[(size_t)e * DZ] = acc[i][j];
        }
    }
}

// ---------------------------------------------------------------------------
extern "C" void kernel_launch(void* const* d_in, const int* in_sizes, int n_in,
                              void* d_out, int out_size)
{
    const float* x  = (const float*)d_in[0];
    const float* y  = (const float*)d_in[1];
    const float* wx = (const float*)d_in[2];
    const float* wy = (const float*)d_in[3];
    const float* wz = (const float*)d_in[4];
    float* out = (float*)d_out;

    GTab gt;
    build_gtab(&gt);

    const int smem_gemm = (2 * 64 * PAK + 2 * KC * 128) * 4;   // 51200 B
    cudaFuncSetAttribute(k_lin_gemm, cudaFuncAttributeMaxDynamicSharedMemorySize, smem_gemm);
    cudaFuncSetAttribute(k_out,      cudaFuncAttributeMaxDynamicSharedMemorySize, smem_gemm);

    k_tr<<<NN / 4, 256>>>(x, y);

    dim3 g1(16, 2 * DX);
    k_lin_gemm<<<g1, 256, smem_gemm>>>(wx, wy);

    k_gaunt<<<NN / 2, 128>>>(gt);

    dim3 g3(16, DZ);
    k_out<<<g3, 256, smem_gemm>>>(wz, out);
}

// round 11
// speedup vs baseline: 1.0289x; 1.0289x over previous
#include <cuda_runtime.h>
#include <math.h>
#include <string.h>
#include <stdint.h>

// Problem constants
#define NN   1024
#define MUL  128
#define CH   128
#define RBq  20
#define RAq  19
#define DX   9     // (L1+1)^2 = (L2+1)^2
#define DZ   25    // (LZ+1)^2
#define MAXG 480

#define SCALE_IN  0.08838834764831845f   // 1/sqrt(128)
#define SCALE_OUT 0.08838834764831845f   // 1/sqrt(128)

// Sparse Gaunt table, passed by value as kernel parameter (constant memory).
struct GTab {
    int   start[DZ + 1];
    int   idx[MAXG];       // (d1 << 8) | d2
    float coef[MAXG];
};

// Intermediates
__device__ float g_xt [NN * DX * MUL];   // x transposed [n][d][m]
__device__ float g_yt [NN * DX * MUL];   // y transposed [n][d][m]
__device__ float g_xct[NN * DX * CH];    // [n][d][c]
__device__ float g_yct[NN * DX * CH];
__device__ float g_zt [NN * DZ * CH];    // [n][d][c]

// ---------------------------------------------------------------------------
// cp.async + f32x2 helpers
// ---------------------------------------------------------------------------
__device__ __forceinline__ void cp_async16(uint32_t dst, const void* src) {
    asm volatile("cp.async.cg.shared.global [%0], [%1], 16;\n" :: "r"(dst), "l"(src));
}
__device__ __forceinline__ void cp_commit() {
    asm volatile("cp.async.commit_group;\n" ::: "memory");
}
template<int N> __device__ __forceinline__ void cp_wait() {
    asm volatile("cp.async.wait_group %0;\n" :: "n"(N) : "memory");
}

// pack the same float into both halves of a 64-bit f32x2 operand
__device__ __forceinline__ unsigned long long bcast2(float a) {
    unsigned long long r;
    unsigned ai = __float_as_uint(a);
    asm("mov.b64 %0, {%1, %1};" : "=l"(r) : "r"(ai));
    return r;
}
// d = a * b + d on packed f32x2 (SASS FFMA2 — 2 MACs/lane, full rate)
__device__ __forceinline__ void fma2(unsigned long long& d,
                                     unsigned long long a, unsigned long long b) {
    asm("fma.rn.f32x2 %0, %1, %2, %0;" : "+l"(d) : "l"(a), "l"(b));
}
__device__ __forceinline__ float2 unpack2(unsigned long long v) {
    unsigned lo, hi;
    asm("mov.b64 {%0, %1}, %2;" : "=r"(lo), "=r"(hi) : "l"(v));
    return make_float2(__uint_as_float(lo), __uint_as_float(hi));
}

// ---------------------------------------------------------------------------
// Host: build the Gaunt table (double precision, exact quadrature as ref)
// ---------------------------------------------------------------------------
static double assoc_legendre_h(int l, int m, double x) {
    double pmm = 1.0;
    if (m > 0) {
        double df = 1.0;
        for (int i = 1; i < 2 * m; i += 2) df *= (double)i;
        pmm = ((m & 1) ? -1.0 : 1.0) * df * pow(1.0 - x * x, 0.5 * m);
    }
    if (l == m) return pmm;
    double pmmp1 = x * (2 * m + 1) * pmm;
    if (l == m + 1) return pmmp1;
    double p = pmmp1;
    for (int ll = m + 2; ll <= l; ++ll) {
        p = ((2 * ll - 1) * x * pmmp1 - (ll + m - 1) * pmm) / (ll - m);
        pmm = pmmp1; pmmp1 = p;
    }
    return pmmp1;
}

static void build_gtab(GTab* gt) {
    double ct[RBq], qw[RBq];
    const int n = RBq;
    for (int i = 0; i < n; ++i) {
        double z = cos(M_PI * (i + 0.75) / (n + 0.5));
        double pp = 1.0;
        for (int it = 0; it < 100; ++it) {
            double p1 = 1.0, p2 = 0.0;
            for (int j = 1; j <= n; ++j) {
                double p3 = p2; p2 = p1;
                p1 = ((2.0 * j - 1.0) * z * p2 - (j - 1.0) * p3) / (double)j;
            }
            pp = n * (z * p1 - p2) / (z * z - 1.0);
            double dz = p1 / pp;
            z -= dz;
            if (fabs(dz) < 1e-15) break;
        }
        ct[i] = z;
        qw[i] = 2.0 / ((1.0 - z * z) * pp * pp);
    }

    static double Y[DZ][RBq][RAq];
    for (int l = 0; l <= 4; ++l) {
        for (int m = -l; m <= l; ++m) {
            int am = m < 0 ? -m : m;
            double f1 = 1.0, f2 = 1.0;
            for (int i = 2; i <= l - am; ++i) f1 *= (double)i;
            for (int i = 2; i <= l + am; ++i) f2 *= (double)i;
            double nlm = sqrt((2.0 * l + 1.0) / (4.0 * M_PI) * f1 / f2);
            for (int b = 0; b < RBq; ++b) {
                double P = assoc_legendre_h(l, am, ct[b]);
                for (int a = 0; a < RAq; ++a) {
                    double alpha = 2.0 * M_PI * (double)a / (double)RAq;
                    double ang;
                    if (m == 0)      ang = 1.0;
                    else if (m > 0)  ang = sqrt(2.0) * cos(m * alpha);
                    else             ang = sqrt(2.0) * sin(am * alpha);
                    Y[l * l + l + m][b][a] = nlm * P * ang;
                }
            }
        }
    }

    int cnt = 0;
    for (int d = 0; d < DZ; ++d) {
        gt->start[d] = cnt;
        for (int d1 = 0; d1 < DX; ++d1) {
            for (int d2 = 0; d2 < DX; ++d2) {
                double s = 0.0;
                for (int b = 0; b < RBq; ++b) {
                    double rs = 0.0;
                    for (int a = 0; a < RAq; ++a)
                        rs += Y[d][b][a] * Y[d1][b][a] * Y[d2][b][a];
                    s += rs * qw[b];
                }
                s *= 2.0 * M_PI / (double)RAq;
                if (fabs(s) > 1e-8 && cnt < MAXG) {
                    gt->idx[cnt]  = (d1 << 8) | d2;
                    gt->coef[cnt] = (float)s;
                    ++cnt;
                }
            }
        }
    }
    gt->start[DZ] = cnt;
    for (int k = cnt; k < MAXG; ++k) { gt->idx[k] = 0; gt->coef[k] = 0.0f; }
}

// ---------------------------------------------------------------------------
// Kernel 0: transpose x,y [n][m][9] -> [n][9][m]. 4 nodes/CTA, 256 threads.
// ---------------------------------------------------------------------------
__global__ void __launch_bounds__(256) k_tr(
    const float* __restrict__ x, const float* __restrict__ y)
{
    __shared__ float sm[4 * MUL * DX];   // 18432 B
    const int tid = threadIdx.x;
    const int n0  = blockIdx.x * 4;
    const int NB  = 4 * MUL * DX;        // 4608

    for (int pass = 0; pass < 2; ++pass) {
        const float* src = pass ? y    : x;
        float*       dst = pass ? g_yt : g_xt;

        __syncthreads();
        for (int i = tid; i < NB; i += 256)
            sm[i] = src[(size_t)n0 * (MUL * DX) + i];
        __syncthreads();
        for (int o = tid; o < NB; o += 256) {
            int j = o / (DX * MUL);
            int r = o - j * (DX * MUL);
            int d = r >> 7;              // r / 128
            int m = r & 127;
            dst[(size_t)n0 * (DX * MUL) + o] = sm[j * (MUL * DX) + m * DX + d];
        }
    }
}

// ---------------------------------------------------------------------------
// Shared GEMM machinery: CTA = 64 rows x 128 cols, K=128 in 4 chunks of 32,
// cp.async double-buffered, 256 threads, 4x8 micro-tile with FFMA2 math.
// ---------------------------------------------------------------------------
#define KC  32
#define PAK 36    // A row pitch (32 + 4): conflict-free, float4-aligned

// issue one stage of cp.async loads (A: 64 rows x KC, B: KC x 128)
__device__ __forceinline__ void gemm_load_stage(
    uint32_t As_u, uint32_t Bs_u, int buf,
    const float* Ab, int ldA, const float* Bb, int ko,
    int ar, int as, int bk, int be4)
{
    cp_async16(As_u + (((buf * 64 + ar)      * PAK + as * 4) << 2),
               Ab + (size_t)ar * ldA + ko + as * 4);
    cp_async16(As_u + (((buf * 64 + ar + 32) * PAK + as * 4) << 2),
               Ab + (size_t)(ar + 32) * ldA + ko + as * 4);
    #pragma unroll
    for (int s = 0; s < 4; ++s)
        cp_async16(Bs_u + (((buf * KC + bk + s * 8) * 128 + be4 * 4) << 2),
                   Bb + (size_t)(ko + bk + s * 8) * CH + be4 * 4);
    cp_commit();
}

// packed-f32x2 compute: per kk, 16 FFMA2 = 64 MACs/thread-kk
__device__ __forceinline__ void gemm_compute_stage(
    const float* __restrict__ A, const float* __restrict__ B,
    int tm, int te, unsigned long long acc2[4][4])
{
    const float* a0p = A + (tm * 4 + 0) * PAK;
    const float* a1p = A + (tm * 4 + 1) * PAK;
    const float* a2p = A + (tm * 4 + 2) * PAK;
    const float* a3p = A + (tm * 4 + 3) * PAK;
    #pragma unroll 8
    for (int kk = 0; kk < KC; ++kk) {
        unsigned long long ap0 = bcast2(a0p[kk]);
        unsigned long long ap1 = bcast2(a1p[kk]);
        unsigned long long ap2 = bcast2(a2p[kk]);
        unsigned long long ap3 = bcast2(a3p[kk]);
        ulonglong2 b0 = *(const ulonglong2*)(B + kk * 128 + te * 4);
        ulonglong2 b1 = *(const ulonglong2*)(B + kk * 128 + 64 + te * 4);
        fma2(acc2[0][0], ap0, b0.x); fma2(acc2[0][1], ap0, b0.y);
        fma2(acc2[0][2], ap0, b1.x); fma2(acc2[0][3], ap0, b1.y);
        fma2(acc2[1][0], ap1, b0.x); fma2(acc2[1][1], ap1, b0.y);
        fma2(acc2[1][2], ap1, b1.x); fma2(acc2[1][3], ap1, b1.y);
        fma2(acc2[2][0], ap2, b0.x); fma2(acc2[2][1], ap2, b0.y);
        fma2(acc2[2][2], ap2, b1.x); fma2(acc2[2][3], ap2, b1.y);
        fma2(acc2[3][0], ap3, b0.x); fma2(acc2[3][1], ap3, b0.y);
        fma2(acc2[3][2], ap3, b1.x); fma2(acc2[3][3], ap3, b1.y);
    }
}

// full mainloop filling acc2[4][4] (packed pairs of e-columns)
__device__ __forceinline__ void gemm_mainloop(
    const float* Ab, int ldA, const float* Bb,
    float* As, float* Bs, int tid, unsigned long long acc2[4][4])
{
    const int ar  = tid >> 3;
    const int as  = tid & 7;
    const int be4 = tid & 31;
    const int bk  = tid >> 5;
    const int tm  = tid >> 4;
    const int te  = tid & 15;

    uint32_t As_u = (uint32_t)__cvta_generic_to_shared(As);
    uint32_t Bs_u = (uint32_t)__cvta_generic_to_shared(Bs);

    #pragma unroll
    for (int i = 0; i < 4; ++i)
        #pragma unroll
        for (int j = 0; j < 4; ++j) acc2[i][j] = 0ull;   // packed (+0,+0)

    gemm_load_stage(As_u, Bs_u, 0, Ab, ldA, Bb, 0,      ar, as, bk, be4);
    gemm_load_stage(As_u, Bs_u, 1, Ab, ldA, Bb, KC,     ar, as, bk, be4);

    // kb = 0
    cp_wait<1>(); __syncthreads();
    gemm_compute_stage(As, Bs, tm, te, acc2);
    __syncthreads();
    gemm_load_stage(As_u, Bs_u, 0, Ab, ldA, Bb, 2 * KC, ar, as, bk, be4);

    // kb = 1
    cp_wait<1>(); __syncthreads();
    gemm_compute_stage(As + 64 * PAK, Bs + KC * 128, tm, te, acc2);
    __syncthreads();
    gemm_load_stage(As_u, Bs_u, 1, Ab, ldA, Bb, 3 * KC, ar, as, bk, be4);

    // kb = 2
    cp_wait<1>(); __syncthreads();
    gemm_compute_stage(As, Bs, tm, te, acc2);

    // kb = 3
    cp_wait<0>(); __syncthreads();
    gemm_compute_stage(As + 64 * PAK, Bs + KC * 128, tm, te, acc2);
}

// ---------------------------------------------------------------------------
// Kernel 1: linear_in as d-batched SGEMM (FFMA2 + cp.async).
// grid (16, 18): b = blockIdx.y -> (tensor, d).
// ---------------------------------------------------------------------------
__global__ void __launch_bounds__(256, 3) k_lin_gemm(
    const float* __restrict__ wx, const float* __restrict__ wy)
{
    extern __shared__ float sm[];
    float* As = sm;                    // [2][64][PAK]
    float* Bs = sm + 2 * 64 * PAK;     // [2][KC][128]

    const int b    = blockIdx.y;
    const int is_y = (b >= DX);
    const int d    = is_y ? (b - DX) : b;
    const int l    = (d >= 4) ? 2 : (d >= 1) ? 1 : 0;
    const int n0   = blockIdx.x * 64;
    const int tid  = threadIdx.x;

    const float* Ab = (is_y ? g_yt : g_xt) + (size_t)n0 * (DX * MUL) + (size_t)d * MUL;
    const float* Bb = (is_y ? wy : wx) + (size_t)l * (MUL * CH);
    float*       Cb = (is_y ? g_yct : g_xct) + (size_t)n0 * (DX * CH) + (size_t)d * CH;

    unsigned long long acc2[4][4];
    gemm_mainloop(Ab, DX * MUL, Bb, As, Bs, tid, acc2);

    const int tm = tid >> 4;
    const int te = tid & 15;
    #pragma unroll
    for (int i = 0; i < 4; ++i) {
        float* cp = Cb + (size_t)(tm * 4 + i) * (DX * CH);
        float2 p0 = unpack2(acc2[i][0]);
        float2 p1 = unpack2(acc2[i][1]);
        float2 p2 = unpack2(acc2[i][2]);
        float2 p3 = unpack2(acc2[i][3]);
        float4 v0 = make_float4(p0.x * SCALE_IN, p0.y * SCALE_IN,
                                p1.x * SCALE_IN, p1.y * SCALE_IN);
        float4 v1 = make_float4(p2.x * SCALE_IN, p2.y * SCALE_IN,
                                p3.x * SCALE_IN, p3.y * SCALE_IN);
        *(float4*)(cp + te * 4)      = v0;
        *(float4*)(cp + 64 + te * 4) = v1;
    }
}

// ---------------------------------------------------------------------------
// Kernel 2: sparse Gaunt contraction. 2 nodes/CTA, 128 threads.
// ---------------------------------------------------------------------------
__global__ void __launch_bounds__(128) k_gaunt(GTab gt)
{
    __shared__ float xcs[2 * DX * CH];
    __shared__ float ycs[2 * DX * CH];

    const int t  = threadIdx.x;
    const int n0 = blockIdx.x * 2;

    for (int i = t; i < 2 * DX * CH; i += 128) {
        xcs[i] = g_xct[(size_t)n0 * DX * CH + i];
        ycs[i] = g_yct[(size_t)n0 * DX * CH + i];
    }
    __syncthreads();

    const float* x0 = xcs + t;
    const float* x1 = xcs + DX * CH + t;
    const float* y0 = ycs + t;
    const float* y1 = ycs + DX * CH + t;
    float* o0 = g_zt + (size_t)n0 * DZ * CH + t;
    float* o1 = o0 + DZ * CH;

    for (int d = 0; d < DZ; ++d) {
        float z0 = 0.0f, z1 = 0.0f;
        const int e0 = gt.start[d], e1 = gt.start[d + 1];
        for (int k = e0; k < e1; ++k) {
            const int   id = gt.idx[k];
            const float cf = gt.coef[k];
            const int a1 = (id >> 8) * CH;
            const int a2 = (id & 255) * CH;
            z0 = fmaf(cf, x0[a1] * y0[a2], z0);
            z1 = fmaf(cf, x1[a1] * y1[a2], z1);
        }
        o0[d * CH] = z0 * SCALE_OUT;
        o1[d * CH] = z1 * SCALE_OUT;
    }
}

// ---------------------------------------------------------------------------
// Kernel 3: linear_out as d-batched SGEMM (FFMA2 + cp.async).
// ---------------------------------------------------------------------------
__global__ void __launch_bounds__(256, 3) k_out(
    const float* __restrict__ wz, float* __restrict__ out)
{
    extern __shared__ float sm[];
    float* As = sm;                    // [2][64][PAK]
    float* Bs = sm + 2 * 64 * PAK;     // [2][KC][128]

    const int d   = blockIdx.y;
    const int l   = (d >= 16) ? 4 : (d >= 9) ? 3 : (d >= 4) ? 2 : (d >= 1) ? 1 : 0;
    const int n0  = blockIdx.x * 64;
    const int tid = threadIdx.x;

    const float* Ab = g_zt + (size_t)n0 * (DZ * CH) + (size_t)d * CH;
    const float* Bb = wz + (size_t)l * (CH * CH);

    unsigned long long acc2[4][4];
    gemm_mainloop(Ab, DZ * CH, Bb, As, Bs, tid, acc2);

    const int tm = tid >> 4;
    const int te = tid & 15;
    // store: out[n][e][d]; acc2[i][q] covers e pairs per mapping below
    #pragma unroll
    for (int i = 0; i < 4; ++i) {
        const int n = n0 + tm * 4 + i;
        float* op = out + (size_t)n * (CH * DZ) + d;
        #pragma unroll
        for (int q = 0; q < 4; ++q) {
            float2 p = unpack2(acc2[i][q]);
            const int e = (q < 2) ? (te * 4 + 2 * q) : (64 + te * 4 + 2 * (q - 2));
            op[(size_t)e * DZ]       = p.x;
            op[(size_t)(e + 1) * DZ] = p.y;
        }
    }
}

// ---------------------------------------------------------------------------
extern "C" void kernel_launch(void* const* d_in, const int* in_sizes, int n_in,
                              void* d_out, int out_size)
{
    const float* x  = (const float*)d_in[0];
    const float* y  = (const float*)d_in[1];
    const float* wx = (const float*)d_in[2];
    const float* wy = (const float*)d_in[3];
    const float* wz = (const float*)d_in[4];
    float* out = (float*)d_out;

    GTab gt;
    build_gtab(&gt);

    const int smem_gemm = (2 * 64 * PAK + 2 * KC * 128) * 4;   // 51200 B
    cudaFuncSetAttribute(k_lin_gemm, cudaFuncAttributeMaxDynamicSharedMemorySize, smem_gemm);
    cudaFuncSetAttribute(k_out,      cudaFuncAttributeMaxDynamicSharedMemorySize, smem_gemm);

    k_tr<<<NN / 4, 256>>>(x, y);

    dim3 g1(16, 2 * DX);
    k_lin_gemm<<<g1, 256, smem_gemm>>>(wx, wy);

    k_gaunt<<<NN / 2, 128>>>(gt);

    dim3 g3(16, DZ);
    k_out<<<g3, 256, smem_gemm>>>(wz, out);
}

// round 12
// speedup vs baseline: 1.1209x; 1.0895x over previous
#include <cuda_runtime.h>
#include <math.h>
#include <string.h>
#include <stdint.h>

// Problem constants
#define NN   1024
#define MUL  128
#define CH   128
#define RBq  20
#define RAq  19
#define DX   9     // (L1+1)^2 = (L2+1)^2
#define DZ   25    // (LZ+1)^2
#define MAXG 480

#define SCALE_IN  0.08838834764831845f   // 1/sqrt(128)
#define SCALE_OUT 0.08838834764831845f   // 1/sqrt(128)

// Sparse Gaunt table, passed by value as kernel parameter (constant memory).
struct GTab {
    int   start[DZ + 1];
    int   idx[MAXG];       // (d1 << 8) | d2
    float coef[MAXG];
};

// Intermediates
__device__ float g_xt [NN * DX * MUL];   // x transposed [n][d][m]
__device__ float g_yt [NN * DX * MUL];   // y transposed [n][d][m]
__device__ float g_xct[NN * DX * CH];    // [n][d][c]
__device__ float g_yct[NN * DX * CH];
__device__ float g_zt [NN * DZ * CH];    // [n][d][c]
__device__ float g_ot [NN * DZ * CH];    // GEMM output [n][d][e] (pre-transpose)

// ---------------------------------------------------------------------------
// cp.async + f32x2 helpers
// ---------------------------------------------------------------------------
__device__ __forceinline__ void cp_async16(uint32_t dst, const void* src) {
    asm volatile("cp.async.cg.shared.global [%0], [%1], 16;\n" :: "r"(dst), "l"(src));
}
__device__ __forceinline__ void cp_commit() {
    asm volatile("cp.async.commit_group;\n" ::: "memory");
}
template<int N> __device__ __forceinline__ void cp_wait() {
    asm volatile("cp.async.wait_group %0;\n" :: "n"(N) : "memory");
}

// pack the same float into both halves of a 64-bit f32x2 operand
__device__ __forceinline__ unsigned long long bcast2(float a) {
    unsigned long long r;
    unsigned ai = __float_as_uint(a);
    asm("mov.b64 %0, {%1, %1};" : "=l"(r) : "r"(ai));
    return r;
}
// d = a * b + d on packed f32x2 (SASS FFMA2 — 2 MACs/lane, full rate)
__device__ __forceinline__ void fma2(unsigned long long& d,
                                     unsigned long long a, unsigned long long b) {
    asm("fma.rn.f32x2 %0, %1, %2, %0;" : "+l"(d) : "l"(a), "l"(b));
}
__device__ __forceinline__ float2 unpack2(unsigned long long v) {
    unsigned lo, hi;
    asm("mov.b64 {%0, %1}, %2;" : "=r"(lo), "=r"(hi) : "l"(v));
    return make_float2(__uint_as_float(lo), __uint_as_float(hi));
}

// ---------------------------------------------------------------------------
// Host: build the Gaunt table (double precision, exact quadrature as ref)
// ---------------------------------------------------------------------------
static double assoc_legendre_h(int l, int m, double x) {
    double pmm = 1.0;
    if (m > 0) {
        double df = 1.0;
        for (int i = 1; i < 2 * m; i += 2) df *= (double)i;
        pmm = ((m & 1) ? -1.0 : 1.0) * df * pow(1.0 - x * x, 0.5 * m);
    }
    if (l == m) return pmm;
    double pmmp1 = x * (2 * m + 1) * pmm;
    if (l == m + 1) return pmmp1;
    double p = pmmp1;
    for (int ll = m + 2; ll <= l; ++ll) {
        p = ((2 * ll - 1) * x * pmmp1 - (ll + m - 1) * pmm) / (ll - m);
        pmm = pmmp1; pmmp1 = p;
    }
    return pmmp1;
}

static void build_gtab(GTab* gt) {
    double ct[RBq], qw[RBq];
    const int n = RBq;
    for (int i = 0; i < n; ++i) {
        double z = cos(M_PI * (i + 0.75) / (n + 0.5));
        double pp = 1.0;
        for (int it = 0; it < 100; ++it) {
            double p1 = 1.0, p2 = 0.0;
            for (int j = 1; j <= n; ++j) {
                double p3 = p2; p2 = p1;
                p1 = ((2.0 * j - 1.0) * z * p2 - (j - 1.0) * p3) / (double)j;
            }
            pp = n * (z * p1 - p2) / (z * z - 1.0);
            double dz = p1 / pp;
            z -= dz;
            if (fabs(dz) < 1e-15) break;
        }
        ct[i] = z;
        qw[i] = 2.0 / ((1.0 - z * z) * pp * pp);
    }

    static double Y[DZ][RBq][RAq];
    for (int l = 0; l <= 4; ++l) {
        for (int m = -l; m <= l; ++m) {
            int am = m < 0 ? -m : m;
            double f1 = 1.0, f2 = 1.0;
            for (int i = 2; i <= l - am; ++i) f1 *= (double)i;
            for (int i = 2; i <= l + am; ++i) f2 *= (double)i;
            double nlm = sqrt((2.0 * l + 1.0) / (4.0 * M_PI) * f1 / f2);
            for (int b = 0; b < RBq; ++b) {
                double P = assoc_legendre_h(l, am, ct[b]);
                for (int a = 0; a < RAq; ++a) {
                    double alpha = 2.0 * M_PI * (double)a / (double)RAq;
                    double ang;
                    if (m == 0)      ang = 1.0;
                    else if (m > 0)  ang = sqrt(2.0) * cos(m * alpha);
                    else             ang = sqrt(2.0) * sin(am * alpha);
                    Y[l * l + l + m][b][a] = nlm * P * ang;
                }
            }
        }
    }

    int cnt = 0;
    for (int d = 0; d < DZ; ++d) {
        gt->start[d] = cnt;
        for (int d1 = 0; d1 < DX; ++d1) {
            for (int d2 = 0; d2 < DX; ++d2) {
                double s = 0.0;
                for (int b = 0; b < RBq; ++b) {
                    double rs = 0.0;
                    for (int a = 0; a < RAq; ++a)
                        rs += Y[d][b][a] * Y[d1][b][a] * Y[d2][b][a];
                    s += rs * qw[b];
                }
                s *= 2.0 * M_PI / (double)RAq;
                if (fabs(s) > 1e-8 && cnt < MAXG) {
                    gt->idx[cnt]  = (d1 << 8) | d2;
                    gt->coef[cnt] = (float)s;
                    ++cnt;
                }
            }
        }
    }
    gt->start[DZ] = cnt;
    for (int k = cnt; k < MAXG; ++k) { gt->idx[k] = 0; gt->coef[k] = 0.0f; }
}

// ---------------------------------------------------------------------------
// Kernel 0: transpose x,y [n][m][9] -> [n][9][m]. 4 nodes/CTA, 256 threads.
// ---------------------------------------------------------------------------
__global__ void __launch_bounds__(256) k_tr(
    const float* __restrict__ x, const float* __restrict__ y)
{
    __shared__ float sm[4 * MUL * DX];   // 18432 B
    const int tid = threadIdx.x;
    const int n0  = blockIdx.x * 4;
    const int NB  = 4 * MUL * DX;        // 4608

    for (int pass = 0; pass < 2; ++pass) {
        const float* src = pass ? y    : x;
        float*       dst = pass ? g_yt : g_xt;

        __syncthreads();
        for (int i = tid; i < NB; i += 256)
            sm[i] = src[(size_t)n0 * (MUL * DX) + i];
        __syncthreads();
        for (int o = tid; o < NB; o += 256) {
            int j = o / (DX * MUL);
            int r = o - j * (DX * MUL);
            int d = r >> 7;              // r / 128
            int m = r & 127;
            dst[(size_t)n0 * (DX * MUL) + o] = sm[j * (MUL * DX) + m * DX + d];
        }
    }
}

// ---------------------------------------------------------------------------
// Shared GEMM machinery: CTA = 64 rows x 128 cols, K=128 in 4 chunks of 32,
// cp.async double-buffered, 256 threads, 4x8 micro-tile with FFMA2 math.
// ---------------------------------------------------------------------------
#define KC  32
#define PAK 36    // A row pitch (32 + 4): conflict-free, float4-aligned

// issue one stage of cp.async loads (A: 64 rows x KC, B: KC x 128)
__device__ __forceinline__ void gemm_load_stage(
    uint32_t As_u, uint32_t Bs_u, int buf,
    const float* Ab, int ldA, const float* Bb, int ko,
    int ar, int as, int bk, int be4)
{
    cp_async16(As_u + (((buf * 64 + ar)      * PAK + as * 4) << 2),
               Ab + (size_t)ar * ldA + ko + as * 4);
    cp_async16(As_u + (((buf * 64 + ar + 32) * PAK + as * 4) << 2),
               Ab + (size_t)(ar + 32) * ldA + ko + as * 4);
    #pragma unroll
    for (int s = 0; s < 4; ++s)
        cp_async16(Bs_u + (((buf * KC + bk + s * 8) * 128 + be4 * 4) << 2),
                   Bb + (size_t)(ko + bk + s * 8) * CH + be4 * 4);
    cp_commit();
}

// packed-f32x2 compute: per kk, 16 FFMA2 = 64 MACs/thread-kk
__device__ __forceinline__ void gemm_compute_stage(
    const float* __restrict__ A, const float* __restrict__ B,
    int tm, int te, unsigned long long acc2[4][4])
{
    const float* a0p = A + (tm * 4 + 0) * PAK;
    const float* a1p = A + (tm * 4 + 1) * PAK;
    const float* a2p = A + (tm * 4 + 2) * PAK;
    const float* a3p = A + (tm * 4 + 3) * PAK;
    #pragma unroll 8
    for (int kk = 0; kk < KC; ++kk) {
        unsigned long long ap0 = bcast2(a0p[kk]);
        unsigned long long ap1 = bcast2(a1p[kk]);
        unsigned long long ap2 = bcast2(a2p[kk]);
        unsigned long long ap3 = bcast2(a3p[kk]);
        ulonglong2 b0 = *(const ulonglong2*)(B + kk * 128 + te * 4);
        ulonglong2 b1 = *(const ulonglong2*)(B + kk * 128 + 64 + te * 4);
        fma2(acc2[0][0], ap0, b0.x); fma2(acc2[0][1], ap0, b0.y);
        fma2(acc2[0][2], ap0, b1.x); fma2(acc2[0][3], ap0, b1.y);
        fma2(acc2[1][0], ap1, b0.x); fma2(acc2[1][1], ap1, b0.y);
        fma2(acc2[1][2], ap1, b1.x); fma2(acc2[1][3], ap1, b1.y);
        fma2(acc2[2][0], ap2, b0.x); fma2(acc2[2][1], ap2, b0.y);
        fma2(acc2[2][2], ap2, b1.x); fma2(acc2[2][3], ap2, b1.y);
        fma2(acc2[3][0], ap3, b0.x); fma2(acc2[3][1], ap3, b0.y);
        fma2(acc2[3][2], ap3, b1.x); fma2(acc2[3][3], ap3, b1.y);
    }
}

// full mainloop filling acc2[4][4] (packed pairs of e-columns)
__device__ __forceinline__ void gemm_mainloop(
    const float* Ab, int ldA, const float* Bb,
    float* As, float* Bs, int tid, unsigned long long acc2[4][4])
{
    const int ar  = tid >> 3;
    const int as  = tid & 7;
    const int be4 = tid & 31;
    const int bk  = tid >> 5;
    const int tm  = tid >> 4;
    const int te  = tid & 15;

    uint32_t As_u = (uint32_t)__cvta_generic_to_shared(As);
    uint32_t Bs_u = (uint32_t)__cvta_generic_to_shared(Bs);

    #pragma unroll
    for (int i = 0; i < 4; ++i)
        #pragma unroll
        for (int j = 0; j < 4; ++j) acc2[i][j] = 0ull;   // packed (+0,+0)

    gemm_load_stage(As_u, Bs_u, 0, Ab, ldA, Bb, 0,      ar, as, bk, be4);
    gemm_load_stage(As_u, Bs_u, 1, Ab, ldA, Bb, KC,     ar, as, bk, be4);

    // kb = 0
    cp_wait<1>(); __syncthreads();
    gemm_compute_stage(As, Bs, tm, te, acc2);
    __syncthreads();
    gemm_load_stage(As_u, Bs_u, 0, Ab, ldA, Bb, 2 * KC, ar, as, bk, be4);

    // kb = 1
    cp_wait<1>(); __syncthreads();
    gemm_compute_stage(As + 64 * PAK, Bs + KC * 128, tm, te, acc2);
    __syncthreads();
    gemm_load_stage(As_u, Bs_u, 1, Ab, ldA, Bb, 3 * KC, ar, as, bk, be4);

    // kb = 2
    cp_wait<1>(); __syncthreads();
    gemm_compute_stage(As, Bs, tm, te, acc2);

    // kb = 3
    cp_wait<0>(); __syncthreads();
    gemm_compute_stage(As + 64 * PAK, Bs + KC * 128, tm, te, acc2);
}

// coalesced float4 store of the 4x8 micro-tile into a [rows][128] row-major C
__device__ __forceinline__ void gemm_store_rows(
    float* Cb, size_t ldC, int tm, int te,
    unsigned long long acc2[4][4], float scale)
{
    #pragma unroll
    for (int i = 0; i < 4; ++i) {
        float* cp = Cb + (size_t)(tm * 4 + i) * ldC;
        float2 p0 = unpack2(acc2[i][0]);
        float2 p1 = unpack2(acc2[i][1]);
        float2 p2 = unpack2(acc2[i][2]);
        float2 p3 = unpack2(acc2[i][3]);
        float4 v0 = make_float4(p0.x * scale, p0.y * scale,
                                p1.x * scale, p1.y * scale);
        float4 v1 = make_float4(p2.x * scale, p2.y * scale,
                                p3.x * scale, p3.y * scale);
        *(float4*)(cp + te * 4)      = v0;
        *(float4*)(cp + 64 + te * 4) = v1;
    }
}

// ---------------------------------------------------------------------------
// Kernel 1: linear_in as d-batched SGEMM (FFMA2 + cp.async).
// grid (16, 18): b = blockIdx.y -> (tensor, d).
// ---------------------------------------------------------------------------
__global__ void __launch_bounds__(256, 3) k_lin_gemm(
    const float* __restrict__ wx, const float* __restrict__ wy)
{
    extern __shared__ float sm[];
    float* As = sm;                    // [2][64][PAK]
    float* Bs = sm + 2 * 64 * PAK;     // [2][KC][128]

    const int b    = blockIdx.y;
    const int is_y = (b >= DX);
    const int d    = is_y ? (b - DX) : b;
    const int l    = (d >= 4) ? 2 : (d >= 1) ? 1 : 0;
    const int n0   = blockIdx.x * 64;
    const int tid  = threadIdx.x;

    const float* Ab = (is_y ? g_yt : g_xt) + (size_t)n0 * (DX * MUL) + (size_t)d * MUL;
    const float* Bb = (is_y ? wy : wx) + (size_t)l * (MUL * CH);
    float*       Cb = (is_y ? g_yct : g_xct) + (size_t)n0 * (DX * CH) + (size_t)d * CH;

    unsigned long long acc2[4][4];
    gemm_mainloop(Ab, DX * MUL, Bb, As, Bs, tid, acc2);

    gemm_store_rows(Cb, DX * CH, tid >> 4, tid & 15, acc2, SCALE_IN);
}

// ---------------------------------------------------------------------------
// Kernel 2: sparse Gaunt contraction. 2 nodes/CTA, 128 threads.
// ---------------------------------------------------------------------------
__global__ void __launch_bounds__(128) k_gaunt(GTab gt)
{
    __shared__ float xcs[2 * DX * CH];
    __shared__ float ycs[2 * DX * CH];

    const int t  = threadIdx.x;
    const int n0 = blockIdx.x * 2;

    for (int i = t; i < 2 * DX * CH; i += 128) {
        xcs[i] = g_xct[(size_t)n0 * DX * CH + i];
        ycs[i] = g_yct[(size_t)n0 * DX * CH + i];
    }
    __syncthreads();

    const float* x0 = xcs + t;
    const float* x1 = xcs + DX * CH + t;
    const float* y0 = ycs + t;
    const float* y1 = ycs + DX * CH + t;
    float* o0 = g_zt + (size_t)n0 * DZ * CH + t;
    float* o1 = o0 + DZ * CH;

    for (int d = 0; d < DZ; ++d) {
        float z0 = 0.0f, z1 = 0.0f;
        const int e0 = gt.start[d], e1 = gt.start[d + 1];
        for (int k = e0; k < e1; ++k) {
            const int   id = gt.idx[k];
            const float cf = gt.coef[k];
            const int a1 = (id >> 8) * CH;
            const int a2 = (id & 255) * CH;
            z0 = fmaf(cf, x0[a1] * y0[a2], z0);
            z1 = fmaf(cf, x1[a1] * y1[a2], z1);
        }
        o0[d * CH] = z0 * SCALE_OUT;
        o1[d * CH] = z1 * SCALE_OUT;
    }
}

// ---------------------------------------------------------------------------
// Kernel 3: linear_out as d-batched SGEMM (FFMA2 + cp.async).
// Writes COALESCED into g_ot[n][d][e]; k_fin transposes to out[n][e][d].
// ---------------------------------------------------------------------------
__global__ void __launch_bounds__(256, 3) k_out(
    const float* __restrict__ wz)
{
    extern __shared__ float sm[];
    float* As = sm;                    // [2][64][PAK]
    float* Bs = sm + 2 * 64 * PAK;     // [2][KC][128]

    const int d   = blockIdx.y;
    const int l   = (d >= 16) ? 4 : (d >= 9) ? 3 : (d >= 4) ? 2 : (d >= 1) ? 1 : 0;
    const int n0  = blockIdx.x * 64;
    const int tid = threadIdx.x;

    const float* Ab = g_zt + (size_t)n0 * (DZ * CH) + (size_t)d * CH;
    const float* Bb = wz + (size_t)l * (CH * CH);
    float*       Cb = g_ot + (size_t)n0 * (DZ * CH) + (size_t)d * CH;

    unsigned long long acc2[4][4];
    gemm_mainloop(Ab, DZ * CH, Bb, As, Bs, tid, acc2);

    gemm_store_rows(Cb, DZ * CH, tid >> 4, tid & 15, acc2, 1.0f);
}

// ---------------------------------------------------------------------------
// Kernel 4: final transpose g_ot[n][d][e] -> out[n][e][d].
// 2 nodes/CTA, 256 threads, padded smem (conflict-light both ways).
// ---------------------------------------------------------------------------
__global__ void __launch_bounds__(256) k_fin(float* __restrict__ out)
{
    __shared__ float sm[2 * DZ * 129];   // 25.8 KB
    const int tid = threadIdx.x;
    const int n0  = blockIdx.x * 2;
    const int NB  = DZ * CH;             // 3200 per node

    #pragma unroll
    for (int j = 0; j < 2; ++j)
        for (int i = tid; i < NB; i += 256) {
            int d = i >> 7;
            int e = i & 127;
            sm[j * DZ * 129 + d * 129 + e] =
                g_ot[(size_t)(n0 + j) * NB + i];
        }
    __syncthreads();
    #pragma unroll
    for (int j = 0; j < 2; ++j)
        for (int o = tid; o < NB; o += 256) {
            int e = o / DZ;
            int d = o - e * DZ;
            out[(size_t)(n0 + j) * NB + o] = sm[j * DZ * 129 + d * 129 + e];
        }
}

// ---------------------------------------------------------------------------
extern "C" void kernel_launch(void* const* d_in, const int* in_sizes, int n_in,
                              void* d_out, int out_size)
{
    const float* x  = (const float*)d_in[0];
    const float* y  = (const float*)d_in[1];
    const float* wx = (const float*)d_in[2];
    const float* wy = (const float*)d_in[3];
    const float* wz = (const float*)d_in[4];
    float* out = (float*)d_out;

    GTab gt;
    build_gtab(&gt);

    const int smem_gemm = (2 * 64 * PAK + 2 * KC * 128) * 4;   // 51200 B
    cudaFuncSetAttribute(k_lin_gemm, cudaFuncAttributeMaxDynamicSharedMemorySize, smem_gemm);
    cudaFuncSetAttribute(k_out,      cudaFuncAttributeMaxDynamicSharedMemorySize, smem_gemm);

    k_tr<<<NN / 4, 256>>>(x, y);

    dim3 g1(16, 2 * DX);
    k_lin_gemm<<<g1, 256, smem_gemm>>>(wx, wy);

    k_gaunt<<<NN / 2, 128>>>(gt);

    dim3 g3(16, DZ);
    k_out<<<g3, 256, smem_gemm>>>(wz);

    k_fin<<<NN / 2, 256>>>(out);
}

// round 13
// speedup vs baseline: 1.1487x; 1.0248x over previous
#include <cuda_runtime.h>
#include <math.h>
#include <string.h>
#include <stdint.h>

// Problem constants
#define NN   1024
#define MUL  128
#define CH   128
#define RBq  20
#define RAq  19
#define DX   9     // (L1+1)^2 = (L2+1)^2
#define DZ   25    // (LZ+1)^2
#define MAXG 480

#define SCALE_IN  0.08838834764831845f   // 1/sqrt(128)
#define SCALE_OUT 0.08838834764831845f   // 1/sqrt(128)

// Sparse Gaunt table, passed by value as kernel parameter (constant memory).
struct GTab {
    int   start[DZ + 1];
    int   idx[MAXG];       // (d1 << 8) | d2
    float coef[MAXG];
};

// Intermediates
__device__ float g_xt [NN * DX * MUL];   // x transposed [n][d][m]
__device__ float g_yt [NN * DX * MUL];   // y transposed [n][d][m]
__device__ float g_xct[NN * DX * CH];    // [n][d][c]
__device__ float g_yct[NN * DX * CH];
__device__ float g_zt [NN * DZ * CH];    // [n][d][c]
__device__ float g_ot [NN * DZ * CH];    // GEMM output [n][d][e] (pre-transpose)

// ---------------------------------------------------------------------------
// cp.async + f32x2 helpers
// ---------------------------------------------------------------------------
__device__ __forceinline__ void cp_async16(uint32_t dst, const void* src) {
    asm volatile("cp.async.cg.shared.global [%0], [%1], 16;\n" :: "r"(dst), "l"(src));
}
__device__ __forceinline__ void cp_commit() {
    asm volatile("cp.async.commit_group;\n" ::: "memory");
}
template<int N> __device__ __forceinline__ void cp_wait() {
    asm volatile("cp.async.wait_group %0;\n" :: "n"(N) : "memory");
}

// pack the same float into both halves of a 64-bit f32x2 operand
__device__ __forceinline__ unsigned long long bcast2(float a) {
    unsigned long long r;
    unsigned ai = __float_as_uint(a);
    asm("mov.b64 %0, {%1, %1};" : "=l"(r) : "r"(ai));
    return r;
}
// d = a * b + d on packed f32x2 (SASS FFMA2 — 2 MACs/lane, full rate)
__device__ __forceinline__ void fma2(unsigned long long& d,
                                     unsigned long long a, unsigned long long b) {
    asm("fma.rn.f32x2 %0, %1, %2, %0;" : "+l"(d) : "l"(a), "l"(b));
}
__device__ __forceinline__ float2 unpack2(unsigned long long v) {
    unsigned lo, hi;
    asm("mov.b64 {%0, %1}, %2;" : "=r"(lo), "=r"(hi) : "l"(v));
    return make_float2(__uint_as_float(lo), __uint_as_float(hi));
}

// ---------------------------------------------------------------------------
// Host: build the Gaunt table (double precision, exact quadrature as ref)
// ---------------------------------------------------------------------------
static double assoc_legendre_h(int l, int m, double x) {
    double pmm = 1.0;
    if (m > 0) {
        double df = 1.0;
        for (int i = 1; i < 2 * m; i += 2) df *= (double)i;
        pmm = ((m & 1) ? -1.0 : 1.0) * df * pow(1.0 - x * x, 0.5 * m);
    }
    if (l == m) return pmm;
    double pmmp1 = x * (2 * m + 1) * pmm;
    if (l == m + 1) return pmmp1;
    double p = pmmp1;
    for (int ll = m + 2; ll <= l; ++ll) {
        p = ((2 * ll - 1) * x * pmmp1 - (ll + m - 1) * pmm) / (ll - m);
        pmm = pmmp1; pmmp1 = p;
    }
    return pmmp1;
}

static void build_gtab(GTab* gt) {
    double ct[RBq], qw[RBq];
    const int n = RBq;
    for (int i = 0; i < n; ++i) {
        double z = cos(M_PI * (i + 0.75) / (n + 0.5));
        double pp = 1.0;
        for (int it = 0; it < 100; ++it) {
            double p1 = 1.0, p2 = 0.0;
            for (int j = 1; j <= n; ++j) {
                double p3 = p2; p2 = p1;
                p1 = ((2.0 * j - 1.0) * z * p2 - (j - 1.0) * p3) / (double)j;
            }
            pp = n * (z * p1 - p2) / (z * z - 1.0);
            double dz = p1 / pp;
            z -= dz;
            if (fabs(dz) < 1e-15) break;
        }
        ct[i] = z;
        qw[i] = 2.0 / ((1.0 - z * z) * pp * pp);
    }

    static double Y[DZ][RBq][RAq];
    for (int l = 0; l <= 4; ++l) {
        for (int m = -l; m <= l; ++m) {
            int am = m < 0 ? -m : m;
            double f1 = 1.0, f2 = 1.0;
            for (int i = 2; i <= l - am; ++i) f1 *= (double)i;
            for (int i = 2; i <= l + am; ++i) f2 *= (double)i;
            double nlm = sqrt((2.0 * l + 1.0) / (4.0 * M_PI) * f1 / f2);
            for (int b = 0; b < RBq; ++b) {
                double P = assoc_legendre_h(l, am, ct[b]);
                for (int a = 0; a < RAq; ++a) {
                    double alpha = 2.0 * M_PI * (double)a / (double)RAq;
                    double ang;
                    if (m == 0)      ang = 1.0;
                    else if (m > 0)  ang = sqrt(2.0) * cos(m * alpha);
                    else             ang = sqrt(2.0) * sin(am * alpha);
                    Y[l * l + l + m][b][a] = nlm * P * ang;
                }
            }
        }
    }

    int cnt = 0;
    for (int d = 0; d < DZ; ++d) {
        gt->start[d] = cnt;
        for (int d1 = 0; d1 < DX; ++d1) {
            for (int d2 = 0; d2 < DX; ++d2) {
                double s = 0.0;
                for (int b = 0; b < RBq; ++b) {
                    double rs = 0.0;
                    for (int a = 0; a < RAq; ++a)
                        rs += Y[d][b][a] * Y[d1][b][a] * Y[d2][b][a];
                    s += rs * qw[b];
                }
                s *= 2.0 * M_PI / (double)RAq;
                if (fabs(s) > 1e-8 && cnt < MAXG) {
                    gt->idx[cnt]  = (d1 << 8) | d2;
                    gt->coef[cnt] = (float)s;
                    ++cnt;
                }
            }
        }
    }
    gt->start[DZ] = cnt;
    for (int k = cnt; k < MAXG; ++k) { gt->idx[k] = 0; gt->coef[k] = 0.0f; }
}

// ---------------------------------------------------------------------------
// Kernel 0: transpose x,y [n][m][9] -> [n][9][m]. 4 nodes/CTA, 256 threads.
// ---------------------------------------------------------------------------
__global__ void __launch_bounds__(256) k_tr(
    const float* __restrict__ x, const float* __restrict__ y)
{
    __shared__ float sm[4 * MUL * DX];   // 18432 B
    const int tid = threadIdx.x;
    const int n0  = blockIdx.x * 4;
    const int NB  = 4 * MUL * DX;        // 4608

    for (int pass = 0; pass < 2; ++pass) {
        const float* src = pass ? y    : x;
        float*       dst = pass ? g_yt : g_xt;

        __syncthreads();
        for (int i = tid; i < NB; i += 256)
            sm[i] = src[(size_t)n0 * (MUL * DX) + i];
        __syncthreads();
        for (int o = tid; o < NB; o += 256) {
            int j = o / (DX * MUL);
            int r = o - j * (DX * MUL);
            int d = r >> 7;              // r / 128
            int m = r & 127;
            dst[(size_t)n0 * (DX * MUL) + o] = sm[j * (MUL * DX) + m * DX + d];
        }
    }
}

// ---------------------------------------------------------------------------
// Shared GEMM machinery: CTA = 32 rows x 128 cols, K=128 in 4 chunks of 32,
// cp.async double-buffered, 128 threads, 4x8 micro-tile with FFMA2 math.
// smem = 2*32*PAK + 2*KC*128 floats = 41984 B -> 5 CTAs/SM.
// ---------------------------------------------------------------------------
#define TM  32    // rows per CTA
#define KC  32
#define PAK 36    // A row pitch (32 + 4): conflict-free, float4-aligned

// issue one stage of cp.async loads (A: TM rows x KC, B: KC x 128)
__device__ __forceinline__ void gemm_load_stage(
    uint32_t As_u, uint32_t Bs_u, int buf,
    const float* Ab, int ldA, const float* Bb, int ko,
    int ar, int as, int bk, int be4)
{
    // A: 32 rows x 8 float4-slots; 128 threads -> 2 each (slots as, as+4)
    cp_async16(As_u + (((buf * TM + ar) * PAK + as * 4) << 2),
               Ab + (size_t)ar * ldA + ko + as * 4);
    cp_async16(As_u + (((buf * TM + ar) * PAK + as * 4 + 16) << 2),
               Ab + (size_t)ar * ldA + ko + (as + 4) * 4);
    // B: 32 k-rows x 32 float4-cols; 128 threads -> 8 each
    #pragma unroll
    for (int s = 0; s < 8; ++s)
        cp_async16(Bs_u + (((buf * KC + bk + s * 4) * 128 + be4 * 4) << 2),
                   Bb + (size_t)(ko + bk + s * 4) * CH + be4 * 4);
    cp_commit();
}

// packed-f32x2 compute: per kk, 16 FFMA2 = 64 MACs/thread-kk
__device__ __forceinline__ void gemm_compute_stage(
    const float* __restrict__ A, const float* __restrict__ B,
    int tm, int te, unsigned long long acc2[4][4])
{
    const float* a0p = A + (tm * 4 + 0) * PAK;
    const float* a1p = A + (tm * 4 + 1) * PAK;
    const float* a2p = A + (tm * 4 + 2) * PAK;
    const float* a3p = A + (tm * 4 + 3) * PAK;
    #pragma unroll 8
    for (int kk = 0; kk < KC; ++kk) {
        unsigned long long ap0 = bcast2(a0p[kk]);
        unsigned long long ap1 = bcast2(a1p[kk]);
        unsigned long long ap2 = bcast2(a2p[kk]);
        unsigned long long ap3 = bcast2(a3p[kk]);
        ulonglong2 b0 = *(const ulonglong2*)(B + kk * 128 + te * 4);
        ulonglong2 b1 = *(const ulonglong2*)(B + kk * 128 + 64 + te * 4);
        fma2(acc2[0][0], ap0, b0.x); fma2(acc2[0][1], ap0, b0.y);
        fma2(acc2[0][2], ap0, b1.x); fma2(acc2[0][3], ap0, b1.y);
        fma2(acc2[1][0], ap1, b0.x); fma2(acc2[1][1], ap1, b0.y);
        fma2(acc2[1][2], ap1, b1.x); fma2(acc2[1][3], ap1, b1.y);
        fma2(acc2[2][0], ap2, b0.x); fma2(acc2[2][1], ap2, b0.y);
        fma2(acc2[2][2], ap2, b1.x); fma2(acc2[2][3], ap2, b1.y);
        fma2(acc2[3][0], ap3, b0.x); fma2(acc2[3][1], ap3, b0.y);
        fma2(acc2[3][2], ap3, b1.x); fma2(acc2[3][3], ap3, b1.y);
    }
}

// full mainloop filling acc2[4][4] (packed pairs of e-columns)
__device__ __forceinline__ void gemm_mainloop(
    const float* Ab, int ldA, const float* Bb,
    float* As, float* Bs, int tid, unsigned long long acc2[4][4])
{
    const int ar  = tid >> 2;     // 0..31 : A row
    const int as  = tid & 3;      // A float4 slot (and +4)
    const int be4 = tid & 31;     // B float4 col
    const int bk  = tid >> 5;     // 0..3  : B k row (+4 per sweep)
    const int tm  = tid >> 4;     // 0..7  -> rows tm*4 .. tm*4+3
    const int te  = tid & 15;

    uint32_t As_u = (uint32_t)__cvta_generic_to_shared(As);
    uint32_t Bs_u = (uint32_t)__cvta_generic_to_shared(Bs);

    #pragma unroll
    for (int i = 0; i < 4; ++i)
        #pragma unroll
        for (int j = 0; j < 4; ++j) acc2[i][j] = 0ull;   // packed (+0,+0)

    gemm_load_stage(As_u, Bs_u, 0, Ab, ldA, Bb, 0,      ar, as, bk, be4);
    gemm_load_stage(As_u, Bs_u, 1, Ab, ldA, Bb, KC,     ar, as, bk, be4);

    // kb = 0
    cp_wait<1>(); __syncthreads();
    gemm_compute_stage(As, Bs, tm, te, acc2);
    __syncthreads();
    gemm_load_stage(As_u, Bs_u, 0, Ab, ldA, Bb, 2 * KC, ar, as, bk, be4);

    // kb = 1
    cp_wait<1>(); __syncthreads();
    gemm_compute_stage(As + TM * PAK, Bs + KC * 128, tm, te, acc2);
    __syncthreads();
    gemm_load_stage(As_u, Bs_u, 1, Ab, ldA, Bb, 3 * KC, ar, as, bk, be4);

    // kb = 2
    cp_wait<1>(); __syncthreads();
    gemm_compute_stage(As, Bs, tm, te, acc2);

    // kb = 3
    cp_wait<0>(); __syncthreads();
    gemm_compute_stage(As + TM * PAK, Bs + KC * 128, tm, te, acc2);
}

// coalesced float4 store of the 4x8 micro-tile into a [rows][128] row-major C
__device__ __forceinline__ void gemm_store_rows(
    float* Cb, size_t ldC, int tm, int te,
    unsigned long long acc2[4][4], float scale)
{
    #pragma unroll
    for (int i = 0; i < 4; ++i) {
        float* cp = Cb + (size_t)(tm * 4 + i) * ldC;
        float2 p0 = unpack2(acc2[i][0]);
        float2 p1 = unpack2(acc2[i][1]);
        float2 p2 = unpack2(acc2[i][2]);
        float2 p3 = unpack2(acc2[i][3]);
        float4 v0 = make_float4(p0.x * scale, p0.y * scale,
                                p1.x * scale, p1.y * scale);
        float4 v1 = make_float4(p2.x * scale, p2.y * scale,
                                p3.x * scale, p3.y * scale);
        *(float4*)(cp + te * 4)      = v0;
        *(float4*)(cp + 64 + te * 4) = v1;
    }
}

// ---------------------------------------------------------------------------
// Kernel 1: linear_in as d-batched SGEMM (FFMA2 + cp.async).
// grid (32, 18): b = blockIdx.y -> (tensor, d).
// ---------------------------------------------------------------------------
__global__ void __launch_bounds__(128, 5) k_lin_gemm(
    const float* __restrict__ wx, const float* __restrict__ wy)
{
    extern __shared__ float sm[];
    float* As = sm;                    // [2][TM][PAK]
    float* Bs = sm + 2 * TM * PAK;     // [2][KC][128]

    const int b    = blockIdx.y;
    const int is_y = (b >= DX);
    const int d    = is_y ? (b - DX) : b;
    const int l    = (d >= 4) ? 2 : (d >= 1) ? 1 : 0;
    const int n0   = blockIdx.x * TM;
    const int tid  = threadIdx.x;

    const float* Ab = (is_y ? g_yt : g_xt) + (size_t)n0 * (DX * MUL) + (size_t)d * MUL;
    const float* Bb = (is_y ? wy : wx) + (size_t)l * (MUL * CH);
    float*       Cb = (is_y ? g_yct : g_xct) + (size_t)n0 * (DX * CH) + (size_t)d * CH;

    unsigned long long acc2[4][4];
    gemm_mainloop(Ab, DX * MUL, Bb, As, Bs, tid, acc2);

    gemm_store_rows(Cb, DX * CH, tid >> 4, tid & 15, acc2, SCALE_IN);
}

// ---------------------------------------------------------------------------
// Kernel 2: sparse Gaunt contraction. 2 nodes/CTA, 128 threads.
// ---------------------------------------------------------------------------
__global__ void __launch_bounds__(128) k_gaunt(GTab gt)
{
    __shared__ float xcs[2 * DX * CH];
    __shared__ float ycs[2 * DX * CH];

    const int t  = threadIdx.x;
    const int n0 = blockIdx.x * 2;

    for (int i = t; i < 2 * DX * CH; i += 128) {
        xcs[i] = g_xct[(size_t)n0 * DX * CH + i];
        ycs[i] = g_yct[(size_t)n0 * DX * CH + i];
    }
    __syncthreads();

    const float* x0 = xcs + t;
    const float* x1 = xcs + DX * CH + t;
    const float* y0 = ycs + t;
    const float* y1 = ycs + DX * CH + t;
    float* o0 = g_zt + (size_t)n0 * DZ * CH + t;
    float* o1 = o0 + DZ * CH;

    for (int d = 0; d < DZ; ++d) {
        float z0 = 0.0f, z1 = 0.0f;
        const int e0 = gt.start[d], e1 = gt.start[d + 1];
        for (int k = e0; k < e1; ++k) {
            const int   id = gt.idx[k];
            const float cf = gt.coef[k];
            const int a1 = (id >> 8) * CH;
            const int a2 = (id & 255) * CH;
            z0 = fmaf(cf, x0[a1] * y0[a2], z0);
            z1 = fmaf(cf, x1[a1] * y1[a2], z1);
        }
        o0[d * CH] = z0 * SCALE_OUT;
        o1[d * CH] = z1 * SCALE_OUT;
    }
}

// ---------------------------------------------------------------------------
// Kernel 3: linear_out as d-batched SGEMM (FFMA2 + cp.async).
// Writes COALESCED into g_ot[n][d][e]; k_fin transposes to out[n][e][d].
// ---------------------------------------------------------------------------
__global__ void __launch_bounds__(128, 5) k_out(
    const float* __restrict__ wz)
{
    extern __shared__ float sm[];
    float* As = sm;                    // [2][TM][PAK]
    float* Bs = sm + 2 * TM * PAK;     // [2][KC][128]

    const int d   = blockIdx.y;
    const int l   = (d >= 16) ? 4 : (d >= 9) ? 3 : (d >= 4) ? 2 : (d >= 1) ? 1 : 0;
    const int n0  = blockIdx.x * TM;
    const int tid = threadIdx.x;

    const float* Ab = g_zt + (size_t)n0 * (DZ * CH) + (size_t)d * CH;
    const float* Bb = wz + (size_t)l * (CH * CH);
    float*       Cb = g_ot + (size_t)n0 * (DZ * CH) + (size_t)d * CH;

    unsigned long long acc2[4][4];
    gemm_mainloop(Ab, DZ * CH, Bb, As, Bs, tid, acc2);

    gemm_store_rows(Cb, DZ * CH, tid >> 4, tid & 15, acc2, 1.0f);
}

// ---------------------------------------------------------------------------
// Kernel 4: final transpose g_ot[n][d][e] -> out[n][e][d].
// 2 nodes/CTA, 256 threads, padded smem (conflict-light both ways).
// ---------------------------------------------------------------------------
__global__ void __launch_bounds__(256) k_fin(float* __restrict__ out)
{
    __shared__ float sm[2 * DZ * 129];   // 25.8 KB
    const int tid = threadIdx.x;
    const int n0  = blockIdx.x * 2;
    const int NB  = DZ * CH;             // 3200 per node

    #pragma unroll
    for (int j = 0; j < 2; ++j)
        for (int i = tid; i < NB; i += 256) {
            int d = i >> 7;
            int e = i & 127;
            sm[j * DZ * 129 + d * 129 + e] =
                g_ot[(size_t)(n0 + j) * NB + i];
        }
    __syncthreads();
    #pragma unroll
    for (int j = 0; j < 2; ++j)
        for (int o = tid; o < NB; o += 256) {
            int e = o / DZ;
            int d = o - e * DZ;
            out[(size_t)(n0 + j) * NB + o] = sm[j * DZ * 129 + d * 129 + e];
        }
}

// ---------------------------------------------------------------------------
extern "C" void kernel_launch(void* const* d_in, const int* in_sizes, int n_in,
                              void* d_out, int out_size)
{
    const float* x  = (const float*)d_in[0];
    const float* y  = (const float*)d_in[1];
    const float* wx = (const float*)d_in[2];
    const float* wy = (const float*)d_in[3];
    const float* wz = (const float*)d_in[4];
    float* out = (float*)d_out;

    GTab gt;
    build_gtab(&gt);

    const int smem_gemm = (2 * TM * PAK + 2 * KC * 128) * 4;   // 41984 B
    cudaFuncSetAttribute(k_lin_gemm, cudaFuncAttributeMaxDynamicSharedMemorySize, smem_gemm);
    cudaFuncSetAttribute(k_out,      cudaFuncAttributeMaxDynamicSharedMemorySize, smem_gemm);

    k_tr<<<NN / 4, 256>>>(x, y);

    dim3 g1(NN / TM, 2 * DX);
    k_lin_gemm<<<g1, 128, smem_gemm>>>(wx, wy);

    k_gaunt<<<NN / 2, 128>>>(gt);

    dim3 g3(NN / TM, DZ);
    k_out<<<g3, 128, smem_gemm>>>(wz);

    k_fin<<<NN / 2, 256>>>(out);
}